// round 4
// baseline (speedup 1.0000x reference)
#include <cuda_runtime.h>

// Inputs (metadata order): x0 [N*D f32], x1 [N*D f32], x_c_0, x_c_1 (unused), y [N i32]
// Output: scalar f32 loss.
//
// loss = sum_i [ y_i * ||x0_i - x1_i||^2 + (1-y_i) * max(0, 1.2 - ||x0_i - x1_i||) ] / (2N)
// (everything else in the reference is dead code w.r.t. the returned value)

#define MAX_N 8192

__device__ float g_row_sq[MAX_N];   // e_dist_sq per row; fully rewritten every call

// ---------------- Kernel 1: per-row squared distance (pure streaming) --------
__global__ __launch_bounds__(256, 8)
void row_sqdist_kernel(const float4* __restrict__ x0,
                       const float4* __restrict__ x1,
                       int Dvec)                 // D / 4
{
    const int row  = blockIdx.x;
    const int lane = threadIdx.x & 31;
    const int wid  = threadIdx.x >> 5;

    const size_t base = (size_t)row * (size_t)Dvec;
    const float4* a = x0 + base;
    const float4* b = x1 + base;

    float s = 0.0f;
    // Dvec = 1024, 256 threads -> 4 iterations; full unroll front-batches
    // 8 independent LDG.128 per thread. __ldcs = evict-first (touched once).
    #pragma unroll 4
    for (int i = threadIdx.x; i < Dvec; i += 256) {
        float4 av = __ldcs(&a[i]);
        float4 bv = __ldcs(&b[i]);
        float dx = av.x - bv.x;
        float dy = av.y - bv.y;
        float dz = av.z - bv.z;
        float dw = av.w - bv.w;
        s = fmaf(dx, dx, s);
        s = fmaf(dy, dy, s);
        s = fmaf(dz, dz, s);
        s = fmaf(dw, dw, s);
    }

    // Warp reduce
    #pragma unroll
    for (int o = 16; o > 0; o >>= 1)
        s += __shfl_xor_sync(0xffffffffu, s, o);

    __shared__ float wsum[8];
    if (lane == 0) wsum[wid] = s;
    __syncthreads();

    if (wid == 0) {
        s = (lane < 8) ? wsum[lane] : 0.0f;
        #pragma unroll
        for (int o = 4; o > 0; o >>= 1)
            s += __shfl_xor_sync(0xffffffffu, s, o);
        if (lane == 0)
            g_row_sq[row] = s;     // plain store; CTA retires immediately
    }
}

// ---------------- Kernel 2: per-row loss + final scalar reduce ---------------
__global__ __launch_bounds__(256, 1)
void finalize_kernel(const int* __restrict__ y,
                     float* __restrict__ out,
                     int N,
                     float inv_2N)
{
    const int lane = threadIdx.x & 31;
    const int wid  = threadIdx.x >> 5;

    float t = 0.0f;
    for (int i = threadIdx.x; i < N; i += 256) {
        const float s  = g_row_sq[i];
        const float yf = (float)y[i];
        const float e_dist    = sqrtf(s);
        const float e_clamped = fmaxf(1.2f - e_dist, 0.0f);
        t += yf * s + (1.0f - yf) * e_clamped;
    }

    #pragma unroll
    for (int o = 16; o > 0; o >>= 1)
        t += __shfl_xor_sync(0xffffffffu, t, o);

    __shared__ float wsum[8];
    if (lane == 0) wsum[wid] = t;
    __syncthreads();

    if (wid == 0) {
        t = (lane < 8) ? wsum[lane] : 0.0f;
        #pragma unroll
        for (int o = 4; o > 0; o >>= 1)
            t += __shfl_xor_sync(0xffffffffu, t, o);
        if (lane == 0)
            out[0] = t * inv_2N;
    }
}

extern "C" void kernel_launch(void* const* d_in, const int* in_sizes, int n_in,
                              void* d_out, int out_size) {
    const float* x0 = (const float*)d_in[0];
    const float* x1 = (const float*)d_in[1];
    const int*   y  = (const int*)d_in[4];
    float* out = (float*)d_out;

    const int N = in_sizes[4];          // 4096
    const int D = in_sizes[0] / N;      // 4096
    const int Dvec = D / 4;             // 1024
    const float inv_2N = 0.5f / (float)N;

    row_sqdist_kernel<<<N, 256>>>((const float4*)x0, (const float4*)x1, Dvec);
    finalize_kernel<<<1, 256>>>(y, out, N, inv_2N);
}

// round 5
// speedup vs baseline: 1.1866x; 1.1866x over previous
#include <cuda_runtime.h>

// Inputs (metadata order): x0 [N*D f32], x1 [N*D f32], x_c_0, x_c_1 (unused), y [N i32]
// Output: scalar f32 loss.
//
// loss = sum_i [ y_i * ||x0_i - x1_i||^2 + (1-y_i) * max(0, 1.2 - ||x0_i - x1_i||) ] / (2N)
// (everything else in the reference is dead code w.r.t. the returned value)

#define MAX_N 8192

__device__ float g_row_loss[MAX_N];   // per-row loss term; fully rewritten every call

// ---------------- Kernel 1: per-row loss term (pure streaming) ---------------
__global__ __launch_bounds__(256, 8)
void row_loss_kernel(const float4* __restrict__ x0,
                     const float4* __restrict__ x1,
                     const int* __restrict__ y,
                     float* __restrict__ out,
                     int Dvec)                 // D / 4
{
    const int row  = blockIdx.x;
    const int lane = threadIdx.x & 31;
    const int wid  = threadIdx.x >> 5;

    // Zero the output accumulator once; kernel 2 runs strictly after this
    // kernel completes, so ordering is guaranteed.
    if (row == 0 && threadIdx.x == 0) out[0] = 0.0f;

    // Hoisted broadcast label load (L1 hit), off the critical path.
    const float yf = (float)y[row];

    const size_t base = (size_t)row * (size_t)Dvec;
    const float4* a = x0 + base;
    const float4* b = x1 + base;

    float s = 0.0f;
    // Dvec = 1024, 256 threads -> 4 iterations; full unroll front-batches
    // 8 independent LDG.128 per thread. __ldcs = evict-first (touched once).
    #pragma unroll 4
    for (int i = threadIdx.x; i < Dvec; i += 256) {
        float4 av = __ldcs(&a[i]);
        float4 bv = __ldcs(&b[i]);
        float dx = av.x - bv.x;
        float dy = av.y - bv.y;
        float dz = av.z - bv.z;
        float dw = av.w - bv.w;
        s = fmaf(dx, dx, s);
        s = fmaf(dy, dy, s);
        s = fmaf(dz, dz, s);
        s = fmaf(dw, dw, s);
    }

    // Warp reduce
    #pragma unroll
    for (int o = 16; o > 0; o >>= 1)
        s += __shfl_xor_sync(0xffffffffu, s, o);

    __shared__ float wsum[8];
    if (lane == 0) wsum[wid] = s;
    __syncthreads();

    if (wid == 0) {
        s = (lane < 8) ? wsum[lane] : 0.0f;
        #pragma unroll
        for (int o = 4; o > 0; o >>= 1)
            s += __shfl_xor_sync(0xffffffffu, s, o);
        if (lane == 0) {
            const float e_dist    = sqrtf(s);
            const float e_clamped = fmaxf(1.2f - e_dist, 0.0f);
            g_row_loss[row] = yf * s + (1.0f - yf) * e_clamped;  // plain store
        }
    }
}

// ---------------- Kernel 2: parallel scalar reduce ---------------------------
// 16 blocks x 256 threads: one row term per thread -> one load, full MLP.
__global__ __launch_bounds__(256, 8)
void finalize_kernel(float* __restrict__ out,
                     int N,
                     float inv_2N)
{
    const int idx  = blockIdx.x * 256 + threadIdx.x;
    const int lane = threadIdx.x & 31;
    const int wid  = threadIdx.x >> 5;

    float t = (idx < N) ? g_row_loss[idx] : 0.0f;

    #pragma unroll
    for (int o = 16; o > 0; o >>= 1)
        t += __shfl_xor_sync(0xffffffffu, t, o);

    __shared__ float wsum[8];
    if (lane == 0) wsum[wid] = t;
    __syncthreads();

    if (wid == 0) {
        t = (lane < 8) ? wsum[lane] : 0.0f;
        #pragma unroll
        for (int o = 4; o > 0; o >>= 1)
            t += __shfl_xor_sync(0xffffffffu, t, o);
        if (lane == 0)
            atomicAdd(out, t * inv_2N);   // 16 atomics total
    }
}

extern "C" void kernel_launch(void* const* d_in, const int* in_sizes, int n_in,
                              void* d_out, int out_size) {
    const float* x0 = (const float*)d_in[0];
    const float* x1 = (const float*)d_in[1];
    const int*   y  = (const int*)d_in[4];
    float* out = (float*)d_out;

    const int N = in_sizes[4];          // 4096
    const int D = in_sizes[0] / N;      // 4096
    const int Dvec = D / 4;             // 1024
    const float inv_2N = 0.5f / (float)N;

    row_loss_kernel<<<N, 256>>>((const float4*)x0, (const float4*)x1, y, out, Dvec);
    finalize_kernel<<<(N + 255) / 256, 256>>>(out, N, inv_2N);
}

// round 6
// speedup vs baseline: 1.2003x; 1.0115x over previous
#include <cuda_runtime.h>

// Inputs (metadata order): x0 [N*D f32], x1 [N*D f32], x_c_0, x_c_1 (unused), y [N i32]
// Output: scalar f32 loss.
//
// loss = sum_i [ y_i * ||x0_i - x1_i||^2 + (1-y_i) * max(0, 1.2 - ||x0_i - x1_i||) ] / (2N)
// (everything else in the reference is dead code w.r.t. the returned value)

#define MAX_N 8192

__device__ float g_row_loss[MAX_N];   // per-row loss term; fully rewritten every call

// ---------------- Kernel 1: per-row loss term (pure streaming) ---------------
__global__ __launch_bounds__(256, 8)
void row_loss_kernel(const float4* __restrict__ x0,
                     const float4* __restrict__ x1,
                     const int* __restrict__ y,
                     int Dvec)                 // D / 4
{
    const int row  = blockIdx.x;
    const int lane = threadIdx.x & 31;
    const int wid  = threadIdx.x >> 5;

    // Hoisted broadcast label load (L1 hit), off the critical path.
    const float yf = (float)y[row];

    const size_t base = (size_t)row * (size_t)Dvec;
    const float4* a = x0 + base;
    const float4* b = x1 + base;

    float s = 0.0f;
    // Dvec = 1024, 256 threads -> 4 iterations; full unroll front-batches
    // 8 independent LDG.128 per thread. __ldcs = evict-first (touched once).
    #pragma unroll 4
    for (int i = threadIdx.x; i < Dvec; i += 256) {
        float4 av = __ldcs(&a[i]);
        float4 bv = __ldcs(&b[i]);
        float dx = av.x - bv.x;
        float dy = av.y - bv.y;
        float dz = av.z - bv.z;
        float dw = av.w - bv.w;
        s = fmaf(dx, dx, s);
        s = fmaf(dy, dy, s);
        s = fmaf(dz, dz, s);
        s = fmaf(dw, dw, s);
    }

    // Warp reduce
    #pragma unroll
    for (int o = 16; o > 0; o >>= 1)
        s += __shfl_xor_sync(0xffffffffu, s, o);

    __shared__ float wsum[8];
    if (lane == 0) wsum[wid] = s;
    __syncthreads();

    if (wid == 0) {
        s = (lane < 8) ? wsum[lane] : 0.0f;
        #pragma unroll
        for (int o = 4; o > 0; o >>= 1)
            s += __shfl_xor_sync(0xffffffffu, s, o);
        if (lane == 0) {
            const float e_dist    = sqrtf(s);
            const float e_clamped = fmaxf(1.2f - e_dist, 0.0f);
            g_row_loss[row] = yf * s + (1.0f - yf) * e_clamped;  // plain store
        }
    }
}

// ---------------- Kernel 2: single-block scalar reduce -----------------------
// 1 block x 1024 threads, one float4 load per thread = one memory round trip.
__global__ __launch_bounds__(1024, 1)
void finalize_kernel(float* __restrict__ out,
                     int Nvec,        // N / 4
                     float inv_2N)
{
    const int lane = threadIdx.x & 31;
    const int wid  = threadIdx.x >> 5;

    float t = 0.0f;
    if (threadIdx.x < Nvec) {
        const float4 v = ((const float4*)g_row_loss)[threadIdx.x];
        t = (v.x + v.y) + (v.z + v.w);
    }

    #pragma unroll
    for (int o = 16; o > 0; o >>= 1)
        t += __shfl_xor_sync(0xffffffffu, t, o);

    __shared__ float wsum[32];
    if (lane == 0) wsum[wid] = t;
    __syncthreads();

    if (wid == 0) {
        t = (lane < 32) ? wsum[lane] : 0.0f;
        #pragma unroll
        for (int o = 16; o > 0; o >>= 1)
            t += __shfl_xor_sync(0xffffffffu, t, o);
        if (lane == 0)
            out[0] = t * inv_2N;   // single plain store; no atomics, no pre-zero
    }
}

extern "C" void kernel_launch(void* const* d_in, const int* in_sizes, int n_in,
                              void* d_out, int out_size) {
    const float* x0 = (const float*)d_in[0];
    const float* x1 = (const float*)d_in[1];
    const int*   y  = (const int*)d_in[4];
    float* out = (float*)d_out;

    const int N = in_sizes[4];          // 4096
    const int D = in_sizes[0] / N;      // 4096
    const int Dvec = D / 4;             // 1024
    const float inv_2N = 0.5f / (float)N;

    row_loss_kernel<<<N, 256>>>((const float4*)x0, (const float4*)x1, y, Dvec);
    finalize_kernel<<<1, 1024>>>(out, N / 4, inv_2N);
}